// round 8
// baseline (speedup 1.0000x reference)
#include <cuda_runtime.h>

#define T_LEN   2048
#define CSTEP   16                      // timesteps per chunk
#define NCHUNK  (T_LEN / CSTEP)         // 128
#define NITER   (NCHUNK + 2)            // 3-deep pipeline: A -> B -> C
#define NGRP_C  (CSTEP / 4)             // float4-groups per chunk (4)

__device__ __forceinline__ float tanh_fast(float x) {
    float y;
    asm("tanh.approx.f32 %0, %1;" : "=f"(y) : "f"(x));
    return y;
}

// State in the x10 domain (WU = 10*wu etc); clips at +-1e5 are exact no-ops
// on reachable values (|state| <= O(T) ~ 2e3).
//
// 3-warp pipeline, one chunk skew per stage, one __syncthreads per iteration:
//   warp0 (A): own LDG double-buffer (distance 2) + WU chain on chunk k
//              -> (REM,D1) float2, ct2 = p - c2*(wu/W)^2
//   warp1 (B): WL chain on chunk k-1 -> (X,D2) float2
//   warp2 (C): WD chain + q on chunk k-2 -> global stores
// No loader stage, no pet/p smem round-trip: A consumes its prefetched
// registers directly. Inter-stage payloads packed as float2 (LDS/STS.64).
__global__ void __launch_bounds__(96, 1) xaj_kernel(
    const float* __restrict__ inputs,
    const float* __restrict__ pwum, const float* __restrict__ pwlm,
    const float* __restrict__ pwdm, const float* __restrict__ pc,
    const float* __restrict__ pb,  const float* __restrict__ pk1,
    const float* __restrict__ pk2, const float* __restrict__ pk3,
    float* __restrict__ out, int B)
{
    __shared__ float2 sRD[2][CSTEP][32];   // (REM, D1)  A -> B
    __shared__ float2 sXD[2][CSTEP][32];   // (X,   D2)  B -> C
    __shared__ float  sCT[3][CSTEP][32];   // ct2        A -> C (distance 2)

    const int lane = threadIdx.x & 31;
    const int wid  = threadIdx.x >> 5;
    const int row  = blockIdx.x * 32 + lane;

    // scalar params (reference arg swap: runoff_production(wu, wd, wl, p,
    // wum, wdm, wlm, b, c))
    const float wum_p = pwum[0] * 19.9f + 0.1f;
    const float wlm_p = pwdm[0] * 30.0f + 60.0f;
    const float wdm_p = pwlm[0] * 60.0f + 60.0f;
    const float W      = wum_p + wlm_p + wdm_p;
    const float invW10 = 0.1f / W;           // x10-state -> w/W
    const float negc2  = -(pc[0] * 0.19f + 0.01f);
    const float negb2  = -(pb[0] * 0.30f + 0.10f);
    const float k1 = pk1[0] * 0.69f + 0.01f;
    const float k2 = pk2[0] * 0.69f + 0.01f;
    const float k3 = pk3[0] * 0.89f + 0.01f;
    const float F  = k1 + 0.5f * k2 * (1.0f - k1)
                   + 0.25f * k3 * (1.0f - k2) * (1.0f - k1);
    const float halfF = 0.5f * F;

    const float4* __restrict__ in4 =
        reinterpret_cast<const float4*>(inputs + (size_t)row * (T_LEN * 3));
    float4* __restrict__ out4 =
        reinterpret_cast<float4*>(out + (size_t)row * T_LEN);

    float WU = 0.0f, WL = 0.0f, WD = 0.0f;

    // stage-A double prefetch buffers: buf[k&1] holds chunk k (loaded at k-2)
    float4 buf[2][NGRP_C][3];
    if (wid == 0) {
        #pragma unroll
        for (int j = 0; j < NGRP_C; ++j) {
            buf[0][j][0] = in4[j * 3 + 0];
            buf[0][j][1] = in4[j * 3 + 1];
            buf[0][j][2] = in4[j * 3 + 2];
        }
        #pragma unroll
        for (int j = 0; j < NGRP_C; ++j) {
            const int g = NGRP_C + j;
            buf[1][j][0] = in4[g * 3 + 0];
            buf[1][j][1] = in4[g * 3 + 1];
            buf[1][j][2] = in4[g * 3 + 2];
        }
    }

    for (int k = 0; k < NITER; ++k) {
        if (wid == 0) {
            // ---- stage A: WU chain on chunk k (registers), LDG chunk k+2 ----
            if (k < NCHUNK) {
                const int slot = k & 1, cslot = k % 3;
                float4 (*f)[3] = buf[k & 1];
                #pragma unroll
                for (int j = 0; j < NGRP_C; ++j) {
                    // (B,T,3): pet = ch0, p = ch2
                    const float pet_[4] = { f[j][0].x, f[j][0].w,
                                            f[j][1].z, f[j][2].y };
                    const float pr_ [4] = { f[j][0].z, f[j][1].y,
                                            f[j][2].x, f[j][2].w };
                    #pragma unroll
                    for (int i = 0; i < 4; ++i) {
                        const int   t     = j * 4 + i;
                        const float pet10 = 10.0f * pet_[i];
                        const float p10   = 10.0f * pr_[i];
                        const float a    = WU - pet10;          // chain
                        const float ha   = 0.5f * a;
                        const float ct   = fmaf(-0.5f, pet10, p10);
                        const float base = fmaf(0.5f, WU, ct);
                        const float sum  = WU + p10;
                        const float t1   = tanh_fast(a);
                        const float WUn  = fmaf(t1, ha, base);  // carried 24cyc
                        const float ET1  = sum - WUn;           // off-chain
                        const float Z    = pet10 - ET1;
                        const float tr   = tanh_fast(Z);
                        const float hZ   = 0.5f * Z;
                        const float REM  = fmaf(tr, hZ, hZ);
                        const float D1   = p10 - ET1;
                        const float u    = WUn * invW10;        // wu/W
                        const float cu   = negc2 * u;
                        const float ct2  = fmaf(cu, u, pr_[i]); // p - c2*u^2
                        sRD[slot][t][lane]  = make_float2(REM, D1);
                        sCT[cslot][t][lane] = ct2;
                        WU = WUn;
                    }
                }
                if (k + 2 < NCHUNK) {
                    #pragma unroll
                    for (int j = 0; j < NGRP_C; ++j) {
                        const int g = (k + 2) * NGRP_C + j;
                        f[j][0] = in4[g * 3 + 0];
                        f[j][1] = in4[g * 3 + 1];
                        f[j][2] = in4[g * 3 + 2];
                    }
                }
            }
        } else if (wid == 1) {
            // ---- stage B: WL chain on chunk k-1 ----
            if (k >= 1 && k <= NCHUNK) {
                const int kb = k - 1, slot = kb & 1;
                #pragma unroll 4
                for (int t = 0; t < CSTEP; ++t) {
                    const float2 rd  = sRD[slot][t][lane];
                    const float REM  = rd.x;
                    const float D1   = rd.y;
                    const float t3   = tanh_fast(REM);           // off-chain
                    const float g3   = fmaf(t3, 0.5f, 0.5f);     // H(rem)
                    // carried chain (24cyc): aB -> t2 -> WLn
                    const float aB   = REM - WL;
                    const float t2   = tanh_fast(aB);
                    const float haB  = 0.5f * aB;
                    const float gh   = g3 * haB;
                    const float mB   = fmaf(0.5f, WL, 0.5f * REM);
                    const float g3mB = g3 * mB;
                    const float WLD  = WL + D1;
                    WL = fmaf(t2, gh, WLD - g3mB);               // WL + D1 - ET2
                    // X = REM - ET2, D2 = D1 - ET2 (ET2 = g3mB - t2*gh)
                    const float X  = fmaf(t2, gh, REM - g3mB);
                    const float D2 = fmaf(t2, gh, D1  - g3mB);
                    sXD[slot][t][lane] = make_float2(X, D2);
                }
            }
        } else if (wid == 2) {
            // ---- stage C: WD chain + runoff/q on chunk k-2 ----
            if (k >= 2) {
                const int kc = k - 2, slot = kc & 1, cslot = kc % 3;
                #pragma unroll
                for (int j = 0; j < NGRP_C; ++j) {
                    float qv[4];
                    #pragma unroll
                    for (int i = 0; i < 4; ++i) {
                        const int    t   = j * 4 + i;
                        const float2 xd  = sXD[slot][t][lane];
                        const float  X   = xd.x;
                        const float  D2  = xd.y;
                        const float  ct2 = sCT[cslot][t][lane];
                        const float t5   = tanh_fast(X);         // off-chain
                        const float g5   = fmaf(t5, 0.5f, 0.5f); // H(x)
                        // carried chain (24cyc): aC -> t4 -> WDn
                        const float aC   = X - WD;
                        const float t4   = tanh_fast(aC);
                        const float haC  = 0.5f * aC;
                        const float gh5  = g5 * haC;
                        const float mC   = fmaf(0.5f, WD, 0.5f * X);
                        const float g5mC = g5 * mC;
                        const float WDD  = WD + D2;
                        const float WDn  = fmaf(t4, gh5, WDD - g5mC);
                        // q (off-chain, pipelines across steps)
                        const float v    = WDn * invW10;         // wd/W
                        const float bv   = negb2 * v;
                        const float dd   = fmaf(bv, v, ct2);     // p - s
                        const float tq   = tanh_fast(10.0f * dd);
                        const float qh   = halfF * dd;
                        qv[i] = fmaf(tq, qh, qh);                // F*H(p-s)*(p-s)
                        WD = WDn;
                    }
                    out4[kc * NGRP_C + j] = make_float4(
                        qv[0], qv[1], qv[2], qv[3]);
                }
            }
        }
        __syncthreads();
    }
}

extern "C" void kernel_launch(void* const* d_in, const int* in_sizes, int n_in,
                              void* d_out, int out_size) {
    const float* inputs = (const float*)d_in[0];
    const float* wum = (const float*)d_in[1];
    const float* wlm = (const float*)d_in[2];
    const float* wdm = (const float*)d_in[3];
    const float* c   = (const float*)d_in[4];
    const float* bb  = (const float*)d_in[5];
    const float* k1  = (const float*)d_in[6];
    const float* k2  = (const float*)d_in[7];
    const float* k3  = (const float*)d_in[8];
    float* out = (float*)d_out;

    const int B = in_sizes[0] / (T_LEN * 3);

    dim3 block(96);                 // 3 warps: A(+load), B, C
    dim3 grid(B / 32);              // 32 rows per block
    xaj_kernel<<<grid, block>>>(inputs, wum, wlm, wdm, c, bb, k1, k2, k3, out, B);
}

// round 9
// speedup vs baseline: 1.2194x; 1.2194x over previous
#include <cuda_runtime.h>

#define T_LEN   2048
#define CSTEP   16                      // timesteps per chunk
#define NCHUNK  (T_LEN / CSTEP)         // 128
#define NITER   (NCHUNK + 3)            // 4-deep pipeline: L -> A -> B -> C
#define NGRP_C  (CSTEP / 4)             // float4-groups per chunk (4)

__device__ __forceinline__ float tanh_fast(float x) {
    float y;
    asm("tanh.approx.f32 %0, %1;" : "=f"(y) : "f"(x));
    return y;
}

// State in the x10 domain (WU = 10*wu etc); clips at +-1e5 are exact no-ops
// on reachable values.
//
// 4-warp pipeline (L/A/B/C, one chunk skew each, one __syncthreads per iter).
// NEW in this round: each compute stage is software-pipelined INTERNALLY:
//   - prologue: input-only work (LDS, gate tanh -> g3h/g5h coefficients)
//   - chain loop: pure 24-cyc recurrence  sub -> tanh -> fma  (state array)
//   - deferred tail (2 steps late): ET/REM/X/q recovery, next-stage gate
//     tanh, STS/STG -- independent of the current chain step, so it fills
//     the chain's stall shadow instead of extending the serial path.
__global__ void __launch_bounds__(128, 1) xaj_kernel(
    const float* __restrict__ inputs,
    const float* __restrict__ pwum, const float* __restrict__ pwlm,
    const float* __restrict__ pwdm, const float* __restrict__ pc,
    const float* __restrict__ pb,  const float* __restrict__ pk1,
    const float* __restrict__ pk2, const float* __restrict__ pk3,
    float* __restrict__ out, int B)
{
    __shared__ float2 sPP[2][CSTEP][32];   // (pet10, p10)  L -> A
    __shared__ float2 sRD[2][CSTEP][32];   // (REM, D1)     A -> B
    __shared__ float2 sXD[2][CSTEP][32];   // (X, D2)       B -> C
    __shared__ float  sG5[2][CSTEP][32];   // g5h = 0.25*tanh(X)+0.25  B -> C
    __shared__ float  sCT[3][CSTEP][32];   // ct2 = p - c2*u^2         A -> C

    const int lane = threadIdx.x & 31;
    const int wid  = threadIdx.x >> 5;
    const int row  = blockIdx.x * 32 + lane;

    // scalar params (reference arg swap: runoff_production(wu, wd, wl, p,
    // wum, wdm, wlm, b, c))
    const float wum_p = pwum[0] * 19.9f + 0.1f;
    const float wlm_p = pwdm[0] * 30.0f + 60.0f;
    const float wdm_p = pwlm[0] * 60.0f + 60.0f;
    const float W      = wum_p + wlm_p + wdm_p;
    const float invW10 = 0.1f / W;           // x10-state -> w/W
    const float negc2  = -(pc[0] * 0.19f + 0.01f);
    const float negb2  = -(pb[0] * 0.30f + 0.10f);
    const float k1 = pk1[0] * 0.69f + 0.01f;
    const float k2 = pk2[0] * 0.69f + 0.01f;
    const float k3 = pk3[0] * 0.89f + 0.01f;
    const float F  = k1 + 0.5f * k2 * (1.0f - k1)
                   + 0.25f * k3 * (1.0f - k2) * (1.0f - k1);
    const float halfF = 0.5f * F;

    const float4* __restrict__ in4 =
        reinterpret_cast<const float4*>(inputs + (size_t)row * (T_LEN * 3));
    float4* __restrict__ out4 =
        reinterpret_cast<float4*>(out + (size_t)row * T_LEN);

    float WU = 0.0f, WL = 0.0f, WD = 0.0f;

    // loader prefetch, distance 2: buf[k&1] holds chunk k (loaded at k-2)
    float4 buf[2][NGRP_C][3];
    if (wid == 3) {
        #pragma unroll
        for (int j = 0; j < NGRP_C; ++j) {
            buf[0][j][0] = in4[j * 3 + 0];
            buf[0][j][1] = in4[j * 3 + 1];
            buf[0][j][2] = in4[j * 3 + 2];
        }
        #pragma unroll
        for (int j = 0; j < NGRP_C; ++j) {
            const int g = NGRP_C + j;
            buf[1][j][0] = in4[g * 3 + 0];
            buf[1][j][1] = in4[g * 3 + 1];
            buf[1][j][2] = in4[g * 3 + 2];
        }
    }

    for (int k = 0; k < NITER; ++k) {
        if (wid == 3) {
            // ---- loader: STS chunk k (packed float2), LDG chunk k+2 ----
            if (k < NCHUNK) {
                const int slot = k & 1;
                float4 (*f)[3] = buf[k & 1];
                #pragma unroll
                for (int j = 0; j < NGRP_C; ++j) {
                    // (B,T,3): pet = ch0, p = ch2
                    const float pet_[4] = { f[j][0].x, f[j][0].w,
                                            f[j][1].z, f[j][2].y };
                    const float pr_ [4] = { f[j][0].z, f[j][1].y,
                                            f[j][2].x, f[j][2].w };
                    #pragma unroll
                    for (int i = 0; i < 4; ++i)
                        sPP[slot][j * 4 + i][lane] =
                            make_float2(10.0f * pet_[i], 10.0f * pr_[i]);
                }
                if (k + 2 < NCHUNK) {
                    #pragma unroll
                    for (int j = 0; j < NGRP_C; ++j) {
                        const int g = (k + 2) * NGRP_C + j;
                        f[j][0] = in4[g * 3 + 0];
                        f[j][1] = in4[g * 3 + 1];
                        f[j][2] = in4[g * 3 + 2];
                    }
                }
            }
        } else if (wid == 0) {
            // ---- stage A: WU chain, chunk k-1 ----
            if (k >= 1 && k <= NCHUNK) {
                const int ka = k - 1, slot = ka & 1, cslot = ka % 3;
                float pets[CSTEP], ps[CSTEP];
                #pragma unroll
                for (int t = 0; t < CSTEP; ++t) {
                    const float2 pp = sPP[slot][t][lane];
                    pets[t] = pp.x;
                    ps[t]   = pp.y;
                }
                float WUs[CSTEP + 1];
                WUs[0] = WU;
                auto tailA = [&](int u) {
                    const float ET1 = (WUs[u] + ps[u]) - WUs[u + 1];
                    const float Z   = pets[u] - ET1;
                    const float tr  = tanh_fast(Z);
                    const float hZ  = 0.5f * Z;
                    const float REM = fmaf(tr, hZ, hZ);
                    const float D1  = ps[u] - ET1;
                    const float uu  = WUs[u + 1] * invW10;       // wu/W
                    const float ct2 = fmaf(negc2 * uu, uu, 0.1f * ps[u]);
                    sRD[slot][u][lane]  = make_float2(REM, D1);
                    sCT[cslot][u][lane] = ct2;
                };
                #pragma unroll
                for (int t = 0; t < CSTEP; ++t) {
                    // carried chain: a -> tanh -> fma   (24 cyc)
                    const float a    = WUs[t] - pets[t];
                    const float ha   = 0.5f * a;
                    const float base = fmaf(0.5f, WUs[t],
                                            fmaf(-0.5f, pets[t], ps[t]));
                    const float t1   = tanh_fast(a);
                    WUs[t + 1] = fmaf(t1, ha, base);
                    if (t >= 2) tailA(t - 2);
                }
                tailA(CSTEP - 2);
                tailA(CSTEP - 1);
                WU = WUs[CSTEP];
            }
        } else if (wid == 1) {
            // ---- stage B: WL chain, chunk k-2 ----
            if (k >= 2 && k <= NCHUNK + 1) {
                const int kb = k - 2, slot = kb & 1;
                float REMs[CSTEP], D1s[CSTEP], g3hs[CSTEP];
                #pragma unroll
                for (int t = 0; t < CSTEP; ++t) {
                    const float2 rd = sRD[slot][t][lane];
                    REMs[t] = rd.x;
                    D1s[t]  = rd.y;
                    g3hs[t] = fmaf(tanh_fast(rd.x), 0.25f, 0.25f); // 0.5*H(rem)
                }
                float WLs[CSTEP + 1], t2s[CSTEP];
                WLs[0] = WL;
                auto tailB = [&](int u) {
                    const float ghb = fmaf(-g3hs[u], WLs[u],
                                           g3hs[u] * REMs[u]);    // g3*haB
                    const float ET2 = fmaf(g3hs[u], WLs[u] + REMs[u],
                                           -(t2s[u] * ghb));
                    const float X   = REMs[u] - ET2;
                    const float D2  = D1s[u]  - ET2;
                    const float t5  = tanh_fast(X);               // C's gate
                    sXD[slot][u][lane] = make_float2(X, D2);
                    sG5[slot][u][lane] = fmaf(t5, 0.25f, 0.25f);  // 0.5*H(x)
                };
                #pragma unroll
                for (int t = 0; t < CSTEP; ++t) {
                    // carried chain: aB -> tanh -> fma   (24 cyc)
                    const float aB   = REMs[t] - WLs[t];
                    const float t2   = tanh_fast(aB);
                    const float ghb  = fmaf(-g3hs[t], WLs[t],
                                            g3hs[t] * REMs[t]);
                    const float rest = fmaf(1.0f - g3hs[t], WLs[t],
                                            fmaf(-g3hs[t], REMs[t], D1s[t]));
                    WLs[t + 1] = fmaf(t2, ghb, rest);   // WL + D1 - ET2
                    t2s[t] = t2;
                    if (t >= 2) tailB(t - 2);
                }
                tailB(CSTEP - 2);
                tailB(CSTEP - 1);
                WL = WLs[CSTEP];
            }
        } else {
            // ---- stage C: WD chain + runoff/q, chunk k-3 ----
            if (k >= 3) {
                const int kc = k - 3, slot = kc & 1, cslot = kc % 3;
                float Xs[CSTEP], D2s[CSTEP], g5hs[CSTEP];
                #pragma unroll
                for (int t = 0; t < CSTEP; ++t) {
                    const float2 xd = sXD[slot][t][lane];
                    Xs[t]   = xd.x;
                    D2s[t]  = xd.y;
                    g5hs[t] = sG5[slot][t][lane];
                }
                float WDs[CSTEP + 1], qv[CSTEP];
                WDs[0] = WD;
                auto tailC = [&](int u) {
                    const float v  = WDs[u + 1] * invW10;         // wd/W
                    const float dd = fmaf(negb2 * v, v,
                                          sCT[cslot][u][lane]);   // p - s
                    const float tq = tanh_fast(10.0f * dd);
                    const float qh = halfF * dd;
                    qv[u] = fmaf(tq, qh, qh);        // F * H(p-s) * (p-s)
                };
                #pragma unroll
                for (int t = 0; t < CSTEP; ++t) {
                    // carried chain: aC -> tanh -> fma   (24 cyc)
                    const float aC   = Xs[t] - WDs[t];
                    const float t4   = tanh_fast(aC);
                    const float ghc  = fmaf(-g5hs[t], WDs[t],
                                            g5hs[t] * Xs[t]);
                    const float rest = fmaf(1.0f - g5hs[t], WDs[t],
                                            fmaf(-g5hs[t], Xs[t], D2s[t]));
                    WDs[t + 1] = fmaf(t4, ghc, rest);  // WD + D2 - ET3
                    if (t >= 2) tailC(t - 2);
                }
                tailC(CSTEP - 2);
                tailC(CSTEP - 1);
                WD = WDs[CSTEP];
                #pragma unroll
                for (int j = 0; j < NGRP_C; ++j)
                    out4[kc * NGRP_C + j] = make_float4(
                        qv[j * 4 + 0], qv[j * 4 + 1],
                        qv[j * 4 + 2], qv[j * 4 + 3]);
            }
        }
        __syncthreads();
    }
}

extern "C" void kernel_launch(void* const* d_in, const int* in_sizes, int n_in,
                              void* d_out, int out_size) {
    const float* inputs = (const float*)d_in[0];
    const float* wum = (const float*)d_in[1];
    const float* wlm = (const float*)d_in[2];
    const float* wdm = (const float*)d_in[3];
    const float* c   = (const float*)d_in[4];
    const float* bb  = (const float*)d_in[5];
    const float* k1  = (const float*)d_in[6];
    const float* k2  = (const float*)d_in[7];
    const float* k3  = (const float*)d_in[8];
    float* out = (float*)d_out;

    const int B = in_sizes[0] / (T_LEN * 3);

    dim3 block(128);                // 4 warps: A, B, C, Loader
    dim3 grid(B / 32);              // 32 rows per block
    xaj_kernel<<<grid, block>>>(inputs, wum, wlm, wdm, c, bb, k1, k2, k3, out, B);
}